// round 15
// baseline (speedup 1.0000x reference)
#include <cuda_runtime.h>
#include <cuda_bf16.h>
#include <cstdint>

#define BB 64
#define TT 512
#define DD 1024
#define HH 1024
#define NG 4096  // 4*H

// ---------------- device scratch (allocation-free rule) ---------------------
__device__ float g_xproj[(size_t)BB * TT * NG];             // 512 MB
__device__ __nv_bfloat16 g_x_hi[(size_t)BB * TT * DD];      // x split hi
__device__ __nv_bfloat16 g_x_lo[(size_t)BB * TT * DD];      // x split lo
__device__ __nv_bfloat16 g_wxt_hi[(size_t)NG * DD];         // W_x^T hi [n][k]
__device__ __nv_bfloat16 g_wxt_lo[(size_t)NG * DD];         // W_x^T lo
__device__ __nv_bfloat16 g_wt_hi[(size_t)NG * HH];          // W_h^T hi [n][k]
__device__ __nv_bfloat16 g_wt_lo[(size_t)NG * HH];          // W_h^T lo
__device__ __nv_bfloat16 g_h_hi[2][BB * HH];                // hidden hi
__device__ __nv_bfloat16 g_h_lo[2][BB * HH];                // hidden lo
__device__ unsigned g_bar;                                  // grid barrier

// ---------------- helpers ---------------------------------------------------
__device__ __forceinline__ float tanh_approx(float x) {
    float r;
    asm("tanh.approx.f32 %0, %1;" : "=f"(r) : "f"(x));
    return r;
}
__device__ __forceinline__ float sigmoid_f(float x) {
    return __fdividef(1.0f, 1.0f + __expf(-x));
}
__device__ __forceinline__ uint32_t smem_u32(const void* p) {
    uint32_t a;
    asm("{ .reg .u64 t; cvta.to.shared.u64 t, %1; cvt.u32.u64 %0, t; }"
        : "=r"(a) : "l"(p));
    return a;
}
__device__ __forceinline__ void ldsm4(uint32_t& r0, uint32_t& r1, uint32_t& r2,
                                      uint32_t& r3, uint32_t addr) {
    asm volatile(
        "ldmatrix.sync.aligned.m8n8.x4.shared.b16 {%0,%1,%2,%3}, [%4];"
        : "=r"(r0), "=r"(r1), "=r"(r2), "=r"(r3)
        : "r"(addr));
}
__device__ __forceinline__ void mma_tile(float* d, const uint32_t* a,
                                         const uint32_t* b) {
    asm volatile(
        "mma.sync.aligned.m16n8k16.row.col.f32.bf16.bf16.f32 "
        "{%0,%1,%2,%3}, {%4,%5,%6,%7}, {%8,%9}, {%0,%1,%2,%3};"
        : "+f"(d[0]), "+f"(d[1]), "+f"(d[2]), "+f"(d[3])
        : "r"(a[0]), "r"(a[1]), "r"(a[2]), "r"(a[3]), "r"(b[0]), "r"(b[1]));
}
__device__ __forceinline__ void cp16(uint32_t dst, const void* src) {
    asm volatile("cp.async.cg.shared.global [%0], [%1], 16;" ::"r"(dst),
                 "l"(src));
}
__device__ __forceinline__ void cp_commit() {
    asm volatile("cp.async.commit_group;");
}
template <int N>
__device__ __forceinline__ void cp_wait() {
    asm volatile("cp.async.wait_group %0;" ::"n"(N));
}
#define SW128(x) ((x) ^ (((x) >> 3) & 0x70))

// ---------------- init ------------------------------------------------------
__global__ void init_state_kernel() {
    int i = blockIdx.x * blockDim.x + threadIdx.x;
    if (i == 0) g_bar = 0u;
    if (i < BB * HH) {
        g_h_hi[0][i] = __float2bfloat16(0.0f);
        g_h_lo[0][i] = __float2bfloat16(0.0f);
    }
}

// ------- split + transpose full W into bf16 hi/lo (smem-tiled) --------------
__global__ void wsplit_kernel(const float* __restrict__ W) {
    __shared__ float tile[32][33];
    const int n0 = blockIdx.x * 32;
    const int k0 = blockIdx.y * 32;
    const int tx = threadIdx.x;  // 32
    const int ty = threadIdx.y;  // 8
#pragma unroll
    for (int i = ty; i < 32; i += 8)
        tile[i][tx] = W[(size_t)(k0 + i) * NG + n0 + tx];
    __syncthreads();
#pragma unroll
    for (int i = ty; i < 32; i += 8) {
        int n = n0 + i, k = k0 + tx;
        float w = tile[tx][i];
        __nv_bfloat16 hi = __float2bfloat16(w);
        __nv_bfloat16 lo = __float2bfloat16(w - __bfloat162float(hi));
        if (k < DD) {
            g_wxt_hi[(size_t)n * DD + k] = hi;
            g_wxt_lo[(size_t)n * DD + k] = lo;
        } else {
            g_wt_hi[(size_t)n * HH + (k - DD)] = hi;
            g_wt_lo[(size_t)n * HH + (k - DD)] = lo;
        }
    }
}

// ---------------- split x into bf16 hi/lo -----------------------------------
__global__ void xsplit_kernel(const float* __restrict__ x) {
    size_t i = (size_t)blockIdx.x * blockDim.x + threadIdx.x;  // float4 index
    float4 v = ((const float4*)x)[i];
    float f[4] = {v.x, v.y, v.z, v.w};
    size_t b = i * 4;
#pragma unroll
    for (int j = 0; j < 4; j++) {
        __nv_bfloat16 hi = __float2bfloat16(f[j]);
        g_x_hi[b + j] = hi;
        g_x_lo[b + j] = __float2bfloat16(f[j] - __bfloat162float(hi));
    }
}

// ---------------------------------------------------------------------------
// Xproj = X @ W_x + b via split-bf16 HMMA (3 terms).  Block tile 128m x 128n,
// k-chunk 64, cp.async double-buffered.  Per-buffer regions 16 KB each:
// A_hi | A_lo | B_hi | B_lo = 64 KB; two buffers = 128 KB.
// 8 warps: wm=warp>>1 (m32), wn=warp&1 (n64); per warp 2 m16 x 8 n8 tiles.
// ldmatrix addresses fold the per-ks k-offset INSIDE SW128.
// ---------------------------------------------------------------------------
#define XAL 16384
#define XBH 32768
#define XBL 49152
#define XBUF 65536
#define XP_SMEM 131072

__global__ void __launch_bounds__(256, 1) xproj_mma_kernel(
    const float* __restrict__ bias) {
    extern __shared__ char smem[];
    const uint32_t sbase = smem_u32(smem);
    const int tid = threadIdx.x;
    const int warp = tid >> 5;
    const int lane = tid & 31;
    const int m0 = blockIdx.y * 128;
    const int n0 = blockIdx.x * 128;
    const int wm = warp >> 1;
    const int wn = warp & 1;

    const int srow = tid >> 3;
    const int sc16 = tid & 7;

    auto issue = [&](int kc, int buf) {
        const uint32_t db = sbase + buf * XBUF;
        const size_t ko = (size_t)kc * 64 + sc16 * 8;
#pragma unroll
        for (int p = 0; p < 4; p++) {
            int row = p * 32 + srow;
            uint32_t d = SW128(row * 128 + sc16 * 16);
            size_t sa = (size_t)(m0 + row) * DD + ko;
            size_t sb = (size_t)(n0 + row) * DD + ko;
            cp16(db + d, g_x_hi + sa);
            cp16(db + XAL + d, g_x_lo + sa);
            cp16(db + XBH + d, g_wxt_hi + sb);
            cp16(db + XBL + d, g_wxt_lo + sb);
        }
    };

    const int a_r = (lane & 7) + ((lane >> 3) & 1) * 8;
    const int a_kb = (lane >> 4) * 16;
    const int b_r = (lane & 7) + (lane >> 4) * 8;
    const int b_kb = ((lane >> 3) & 1) * 16;
    uint32_t rowA[2], rowB[4];
#pragma unroll
    for (int mt = 0; mt < 2; mt++)
        rowA[mt] = (uint32_t)(wm * 32 + mt * 16 + a_r) * 128 + a_kb;
#pragma unroll
    for (int g = 0; g < 4; g++)
        rowB[g] = (uint32_t)(wn * 64 + g * 16 + b_r) * 128 + b_kb;

    float acc[2][8][4];
#pragma unroll
    for (int mt = 0; mt < 2; mt++)
#pragma unroll
        for (int nt = 0; nt < 8; nt++)
#pragma unroll
            for (int r = 0; r < 4; r++) acc[mt][nt][r] = 0.0f;

    issue(0, 0);
    cp_commit();

    for (int kc = 0; kc < 16; kc++) {
        const int buf = kc & 1;
        if (kc + 1 < 16) {
            issue(kc + 1, buf ^ 1);
            cp_commit();
            cp_wait<1>();
        } else {
            cp_wait<0>();
        }
        __syncthreads();

        const uint32_t ab = sbase + buf * XBUF;
#pragma unroll
        for (int ks = 0; ks < 4; ks++) {
            const uint32_t kb = ks * 32;
            const uint32_t oA0 = SW128(rowA[0] + kb);
            const uint32_t oA1 = SW128(rowA[1] + kb);
            uint32_t oB[4];
#pragma unroll
            for (int g = 0; g < 4; g++) oB[g] = SW128(rowB[g] + kb);

            uint32_t ah[2][4], al[2][4], bh[8][2], bl[8][2];
            ldsm4(ah[0][0], ah[0][1], ah[0][2], ah[0][3], ab + oA0);
            ldsm4(ah[1][0], ah[1][1], ah[1][2], ah[1][3], ab + oA1);
#pragma unroll
            for (int g = 0; g < 4; g++)
                ldsm4(bh[2 * g][0], bh[2 * g][1], bh[2 * g + 1][0],
                      bh[2 * g + 1][1], ab + XBH + oB[g]);
#pragma unroll
            for (int mt = 0; mt < 2; mt++)
#pragma unroll
                for (int nt = 0; nt < 8; nt++)
                    mma_tile(acc[mt][nt], ah[mt], bh[nt]);
#pragma unroll
            for (int g = 0; g < 4; g++)
                ldsm4(bl[2 * g][0], bl[2 * g][1], bl[2 * g + 1][0],
                      bl[2 * g + 1][1], ab + XBL + oB[g]);
#pragma unroll
            for (int mt = 0; mt < 2; mt++)
#pragma unroll
                for (int nt = 0; nt < 8; nt++)
                    mma_tile(acc[mt][nt], ah[mt], bl[nt]);
            ldsm4(al[0][0], al[0][1], al[0][2], al[0][3], ab + XAL + oA0);
            ldsm4(al[1][0], al[1][1], al[1][2], al[1][3], ab + XAL + oA1);
#pragma unroll
            for (int mt = 0; mt < 2; mt++)
#pragma unroll
                for (int nt = 0; nt < 8; nt++)
                    mma_tile(acc[mt][nt], al[mt], bh[nt]);
        }
        __syncthreads();
    }

#pragma unroll
    for (int mt = 0; mt < 2; mt++)
#pragma unroll
        for (int nt = 0; nt < 8; nt++) {
            int m = m0 + wm * 32 + mt * 16 + (lane >> 2);
            int n = n0 + wn * 64 + nt * 8 + (lane & 3) * 2;
            float b0 = bias[n], b1 = bias[n + 1];
            float2 v0 = make_float2(acc[mt][nt][0] + b0, acc[mt][nt][1] + b1);
            float2 v1 = make_float2(acc[mt][nt][2] + b0, acc[mt][nt][3] + b1);
            *(float2*)&g_xproj[(size_t)m * NG + n] = v0;
            *(float2*)&g_xproj[(size_t)(m + 8) * NG + n] = v1;
        }
}

// ---------------------------------------------------------------------------
// Persistent LSTM recurrence: 128 blocks (1/SM), all 512 steps in one launch.
// W_h^T hi/lo resident in smem (128 KB).  Per step: 8 big chunks of k=128
// (two 64-k sub-chunks each), 3-slot x 32 KB cp.async ring, ONE __syncthreads
// per big chunk.  Order per chunk: wait<1> (own groups through chunk kc
// complete) -> __syncthreads (publish everyone's chunk kc; retire slot of
// chunk kc-1) -> stage chunk kc+2 into that slot -> compute chunk kc.
// Cell state c lives in smem (block-private).  3-term split-bf16 HMMA, smem
// k-slice reduction (aliased onto the ring), fused gate epilogue, xv prefetch
// for t+1, global atomic barrier.
// ---------------------------------------------------------------------------
#define W_LO_OFF 65536
#define H_OFF 131072
#define H_SLOT 32768
#define H_SUB 16384
#define H_LO 8192
#define C_OFF (H_OFF + 3 * H_SLOT)   // 229376
#define PERS_SMEM (C_OFF + 2048)     // 231424
#define ZSTR 33

__global__ void __launch_bounds__(256, 1) lstm_persist(float* __restrict__ out) {
    extern __shared__ char smem[];
    const uint32_t sbase = smem_u32(smem);
    const int tid = threadIdx.x;
    const int warp = tid >> 5;
    const int lane = tid & 31;
    const int h0 = blockIdx.x * 8;
    const int ks = warp >> 1;  // k16 slice within 64-k sub-chunk
    const int mh = warp & 1;   // m half

    float* c_smem = (float*)(smem + C_OFF);  // [64][8] block-private cell
    for (int i = tid; i < 512; i += 256) c_smem[i] = 0.0f;

    // ---- preload W_h^T (32 z-cols x 1024 k, hi+lo) into smem ----
    for (int u = tid; u < 4096; u += 256) {
        int kc = u >> 8, r = (u >> 3) & 31, c = u & 7;
        size_t so = (size_t)((r >> 3) * HH + h0 + (r & 7)) * HH + kc * 64 + c * 8;
        uint32_t d = kc * 4096 + SW128(r * 128 + c * 16);
        *(uint4*)(smem + d) = *(const uint4*)&g_wt_hi[so];
        *(uint4*)(smem + W_LO_OFF + d) = *(const uint4*)&g_wt_lo[so];
    }
    __syncthreads();

    // ---- ldmatrix fragment offsets (full k folded inside SW128) ----
    const int a_r = (lane & 7) + ((lane >> 3) & 1) * 8;
    const int a_k = ks * 32 + (lane >> 4) * 16;
    const uint32_t offA0 = SW128((mh * 32 + a_r) * 128 + a_k);
    const uint32_t offA1 = SW128((mh * 32 + 16 + a_r) * 128 + a_k);
    const int b_r = (lane & 7) + (lane >> 4) * 8;
    const int b_k = ks * 32 + ((lane >> 3) & 1) * 16;
    const uint32_t offB0 = SW128(b_r * 128 + b_k);
    const uint32_t offB1 = SW128((16 + b_r) * 128 + b_k);

    // ---- h staging map ----
    const int srow = tid >> 3;
    const int sc16 = tid & 7;
    const uint32_t hd0 = SW128(srow * 128 + sc16 * 16);
    const uint32_t hd1 = SW128((srow + 32) * 128 + sc16 * 16);
    const size_t hs0 = (size_t)srow * HH + sc16 * 8;
    const size_t hs1 = hs0 + (size_t)32 * HH;

    float* zpart = (float*)(smem + H_OFF);  // alias: ring dead at reduce time

    float xv[2][4];
    auto load_xv = [&](int t) {
#pragma unroll
        for (int q = 0; q < 2; q++) {
            int idx = q * 256 + tid;
            const float* xp =
                g_xproj + ((size_t)(idx >> 3) * TT + t) * NG + h0 + (idx & 7);
            xv[q][0] = xp[0];
            xv[q][1] = xp[HH];
            xv[q][2] = xp[2 * HH];
            xv[q][3] = xp[3 * HH];
        }
    };
    load_xv(0);

    for (int t = 0; t < TT; t++) {
        const __nv_bfloat16* hh = g_h_hi[t & 1];
        const __nv_bfloat16* hl = g_h_lo[t & 1];

        auto stage = [&](int kc, int slot) {  // big chunk kc (k=128)
            uint32_t base = sbase + H_OFF + slot * H_SLOT;
#pragma unroll
            for (int sub = 0; sub < 2; sub++) {
                uint32_t d = base + sub * H_SUB;
                int ko = kc * 128 + sub * 64;
                cp16(d + hd0, hh + hs0 + ko);
                cp16(d + hd1, hh + hs1 + ko);
                cp16(d + H_LO + hd0, hl + hs0 + ko);
                cp16(d + H_LO + hd1, hl + hs1 + ko);
            }
        };

        float acc[2][4][4];
#pragma unroll
        for (int mt = 0; mt < 2; mt++)
#pragma unroll
            for (int nt = 0; nt < 4; nt++)
#pragma unroll
                for (int r = 0; r < 4; r++) acc[mt][nt][r] = 0.0f;

        stage(0, 0);
        cp_commit();
        stage(1, 1);
        cp_commit();

        int s_read = 0, s_stage = 2;
        for (int kc = 0; kc < 8; kc++) {
            cp_wait<1>();     // own groups through chunk kc complete
            __syncthreads();  // publish chunk kc; retire slot of chunk kc-1
            if (kc + 2 < 8) stage(kc + 2, s_stage);
            cp_commit();      // empty commits at tail keep arithmetic exact

            const uint32_t slotb = sbase + H_OFF + s_read * H_SLOT;
#pragma unroll
            for (int sub = 0; sub < 2; sub++) {
                const uint32_t ab = slotb + sub * H_SUB;
                const uint32_t wb = sbase + (kc * 2 + sub) * 4096;
                uint32_t ah[2][4], al[2][4], bh[4][2], bl[4][2];
                ldsm4(ah[0][0], ah[0][1], ah[0][2], ah[0][3], ab + offA0);
                ldsm4(ah[1][0], ah[1][1], ah[1][2], ah[1][3], ab + offA1);
                ldsm4(al[0][0], al[0][1], al[0][2], al[0][3],
                      ab + H_LO + offA0);
                ldsm4(al[1][0], al[1][1], al[1][2], al[1][3],
                      ab + H_LO + offA1);
                ldsm4(bh[0][0], bh[0][1], bh[1][0], bh[1][1], wb + offB0);
                ldsm4(bh[2][0], bh[2][1], bh[3][0], bh[3][1], wb + offB1);
                ldsm4(bl[0][0], bl[0][1], bl[1][0], bl[1][1],
                      wb + W_LO_OFF + offB0);
                ldsm4(bl[2][0], bl[2][1], bl[3][0], bl[3][1],
                      wb + W_LO_OFF + offB1);

#pragma unroll
                for (int mt = 0; mt < 2; mt++)
#pragma unroll
                    for (int nt = 0; nt < 4; nt++)
                        mma_tile(acc[mt][nt], ah[mt], bh[nt]);
#pragma unroll
                for (int mt = 0; mt < 2; mt++)
#pragma unroll
                    for (int nt = 0; nt < 4; nt++)
                        mma_tile(acc[mt][nt], ah[mt], bl[nt]);
#pragma unroll
                for (int mt = 0; mt < 2; mt++)
#pragma unroll
                    for (int nt = 0; nt < 4; nt++)
                        mma_tile(acc[mt][nt], al[mt], bh[nt]);
            }
            if (++s_read == 3) s_read = 0;
            if (++s_stage == 3) s_stage = 0;
        }
        __syncthreads();  // retire last chunks before zpart alias writes

        // ---- k-slice partials to smem ----
#pragma unroll
        for (int mt = 0; mt < 2; mt++)
#pragma unroll
            for (int nt = 0; nt < 4; nt++) {
                int m = mh * 32 + mt * 16 + (lane >> 2);
                int n = nt * 8 + (lane & 3) * 2;
                zpart[(ks * 64 + m) * ZSTR + n] = acc[mt][nt][0];
                zpart[(ks * 64 + m) * ZSTR + n + 1] = acc[mt][nt][1];
                zpart[(ks * 64 + m + 8) * ZSTR + n] = acc[mt][nt][2];
                zpart[(ks * 64 + m + 8) * ZSTR + n + 1] = acc[mt][nt][3];
            }
        __syncthreads();

        // ---- fused gate epilogue (c in smem) ----
#pragma unroll
        for (int q = 0; q < 2; q++) {
            int idx = q * 256 + tid;
            int b = idx >> 3;
            int c = idx & 7;
            int hc = h0 + c;

            float zi = xv[q][0], zj = xv[q][1], zf = xv[q][2], zo = xv[q][3];
#pragma unroll
            for (int s = 0; s < 4; s++) {
                const float* zr = zpart + (s * 64 + b) * ZSTR;
                zi += zr[c];
                zj += zr[8 + c];
                zf += zr[16 + c];
                zo += zr[24 + c];
            }

            float cp = c_smem[idx];
            float si = sigmoid_f(zi);
            float sf = sigmoid_f(zf + 1.0f);  // FORGET_BIAS
            float so = sigmoid_f(zo);
            float cn = cp * sf + si * tanh_approx(zj);
            float hn = tanh_approx(cn) * so;

            c_smem[idx] = cn;
            out[((size_t)b * TT + t) * HH + hc] = hn;
            __nv_bfloat16 hi = __float2bfloat16(hn);
            g_h_hi[(t + 1) & 1][b * HH + hc] = hi;
            g_h_lo[(t + 1) & 1][b * HH + hc] =
                __float2bfloat16(hn - __bfloat162float(hi));
        }

        // prefetch next step's xv before the barrier (independent of h)
        if (t + 1 < TT) load_xv(t + 1);

        // ---- grid barrier (skip after last step) ----
        __threadfence();
        __syncthreads();
        if (t + 1 < TT) {
            if (tid == 0) {
                atomicAdd(&g_bar, 1u);
                unsigned target = 128u * (unsigned)(t + 1);
                while (*(volatile unsigned*)&g_bar < target) {
                }
            }
            __syncthreads();
        }
    }
}

// ---------------------------------------------------------------------------
extern "C" void kernel_launch(void* const* d_in, const int* in_sizes, int n_in,
                              void* d_out, int out_size) {
    const float* x = (const float*)d_in[0];   // [B, T, D]
    const float* W = (const float*)d_in[1];   // [D+H, 4H]
    const float* b = (const float*)d_in[2];   // [4H]
    float* out = (float*)d_out;               // [B, T, H]

    cudaFuncSetAttribute(xproj_mma_kernel,
                         cudaFuncAttributeMaxDynamicSharedMemorySize, XP_SMEM);
    cudaFuncSetAttribute(lstm_persist,
                         cudaFuncAttributeMaxDynamicSharedMemorySize, PERS_SMEM);

    init_state_kernel<<<(BB * HH + 255) / 256, 256>>>();
    {
        dim3 wg(NG / 32, (DD + HH) / 32);
        dim3 wb_(32, 8);
        wsplit_kernel<<<wg, wb_>>>(W);
    }
    xsplit_kernel<<<(BB * TT * DD) / 4 / 256, 256>>>(x);

    dim3 xg(NG / 128, (BB * TT) / 128);  // (32, 256)
    xproj_mma_kernel<<<xg, 256, XP_SMEM>>>(b);

    lstm_persist<<<128, 256, PERS_SMEM>>>(out);
}